// round 14
// baseline (speedup 1.0000x reference)
#include <cuda_runtime.h>
#include <cuda_bf16.h>
#include <cstdint>

#define T_STEPS 2048
#define BATCH   64
#define HID     256
#define MROWS   (T_STEPS * BATCH)   // 131072
#define NCHUNK  1024                // 128-row (=2-step) chunks
#define NTILE   (NCHUNK * 2)
#define NPA     42                  // phase-A streams (84 CTAs / 2 halves)
#define NWSTR   10                  // worker streams (20 CTAs / 2 halves)

// GEMM smem layout (bytes) — validated in R7
#define SM_BIAS  0
#define SM_WHI   1024
#define WROWB    264
#define WBYTES   (128 * WROWB * 2)
#define SM_WLO   (SM_WHI + WBYTES)
#define SM_AHI   (SM_WLO + WBYTES)
#define AROWB    72
#define ABYTES   (128 * AROWB * 2)
#define SM_ALO   (SM_AHI + ABYTES)
#define GEMM_SMEM (SM_ALO + ABYTES)  // 173056

// Scan smem: Wt stride 21 float4 (80 floats W + pad): 256*21*16 = 86016 < GEMM_SMEM

__device__ float g_buf0[(size_t)MROWS * HID];   // xp0 fp32
__device__ float g_buf2[(size_t)MROWS * HID];   // xp1 fp32
__device__ __nv_bfloat16 g_h1hi[(size_t)MROWS * HID];
__device__ __nv_bfloat16 g_h1lo[(size_t)MROWS * HID];
__device__ __nv_bfloat16 g_Whi[2][HID * HID];
__device__ __nv_bfloat16 g_Wlo[2][HID * HID];
__device__ int g_prog1[BATCH];
__device__ int g_xp0flag[NTILE];
__device__ int g_midflag[NTILE];

// ---------------------------------------------------------------------------
union F4U { float4 v; unsigned long long u[2]; };
__device__ __forceinline__ unsigned long long ffma2(
    unsigned long long a, unsigned long long b, unsigned long long c)
{
    unsigned long long d;
    asm("fma.rn.f32x2 %0, %1, %2, %3;" : "=l"(d) : "l"(a), "l"(b), "l"(c));
    return d;
}
__device__ __forceinline__ float2 up2(unsigned long long v)
{
    float2 r;
    asm("mov.b64 {%0, %1}, %2;" : "=f"(r.x), "=f"(r.y) : "l"(v));
    return r;
}
__device__ __forceinline__ int ld_acq(const int* p)
{
    int v;
    asm volatile("ld.acquire.gpu.global.b32 %0, [%1];" : "=r"(v) : "l"(p) : "memory");
    return v;
}
__device__ __forceinline__ void st_rel(int* p, int v)
{
    asm volatile("st.release.gpu.global.b32 [%0], %1;" :: "l"(p), "r"(v) : "memory");
}
// Fast tanh: e = exp(2x) via MUFU.EX2, tanh = (e-1)/(e+1) via MUFU.RCP.
// Abs error ~1e-7; clamp avoids overflow (tanh(+-15) == +-1 in fp32).
__device__ __forceinline__ float fast_tanh(float x)
{
    x = fminf(fmaxf(x, -15.0f), 15.0f);
    float e = __expf(2.0f * x);
    return __fdividef(e - 1.0f, e + 1.0f);
}

#define MMA_BF16(d, a, b) \
    asm volatile("mma.sync.aligned.m16n8k16.row.col.f32.bf16.bf16.f32 " \
        "{%0,%1,%2,%3},{%4,%5,%6,%7},{%8,%9},{%0,%1,%2,%3};" \
        : "+f"((d)[0]), "+f"((d)[1]), "+f"((d)[2]), "+f"((d)[3]) \
        : "r"((a)[0]), "r"((a)[1]), "r"((a)[2]), "r"((a)[3]), \
          "r"((b)[0]), "r"((b)[1]))

// ---------------------------------------------------------------------------
// Prep: zero flags, convert W_ih0/W_ih1 to bf16 hi/lo. (~10us)
// ---------------------------------------------------------------------------
__global__ void prep_kernel(const float* __restrict__ Wih0,
                            const float* __restrict__ Wih1)
{
    int idx = blockIdx.x * blockDim.x + threadIdx.x;
    int nthr = gridDim.x * blockDim.x;
    for (int i = idx; i < NTILE; i += nthr) { g_xp0flag[i] = 0; g_midflag[i] = 0; }
    if (idx < BATCH) g_prog1[idx] = 0;
    for (int i = idx; i < 2 * HID * HID; i += nthr) {
        int m = i >> 16, e = i & 0xFFFF;
        float w = (m == 0 ? Wih0 : Wih1)[e];
        __nv_bfloat16 hi = __float2bfloat16(w);
        g_Whi[m][e] = hi;
        g_Wlo[m][e] = __float2bfloat16(w - __bfloat162float(hi));
    }
}

// ---------------------------------------------------------------------------
// Stage W half + bias into smem (validated R7)
// ---------------------------------------------------------------------------
__device__ __forceinline__ void mma_setup_w(
    char* sm, const __nv_bfloat16* Whig, const __nv_bfloat16* Wlog, int bn,
    const float* b1, const float* b2)
{
    const int tid = threadIdx.x;
    const int row = tid >> 1;
    const int seg = tid & 1;
    const uint4* ghi = reinterpret_cast<const uint4*>(
        Whig + (size_t)(bn + row) * 256 + seg * 128);
    const uint4* glo = reinterpret_cast<const uint4*>(
        Wlog + (size_t)(bn + row) * 256 + seg * 128);
    uint4* shi = reinterpret_cast<uint4*>(sm + SM_WHI + row * (WROWB*2) + seg * 256);
    uint4* slo = reinterpret_cast<uint4*>(sm + SM_WLO + row * (WROWB*2) + seg * 256);
    #pragma unroll
    for (int q = 0; q < 16; q++) { shi[q] = ghi[q]; slo[q] = glo[q]; }
    if (tid < 128) {
        int n = bn + tid;
        reinterpret_cast<float*>(sm + SM_BIAS)[tid] = b1[n] + b2[n];
    }
    __syncthreads();
}

// ---------------------------------------------------------------------------
// Shared MMA compute core (validated R7/R10). Variadic: commas OK in STAGE_A.
// ---------------------------------------------------------------------------
#define MMA_CORE_BODY(...)                                                      \
    const int tid  = threadIdx.x;                                               \
    const int lane = tid & 31;                                                  \
    const int wid  = tid >> 5;                                                  \
    const int g    = lane >> 2;                                                 \
    const int tig  = lane & 3;                                                  \
    const int m_base = (wid >> 1) * 32;                                         \
    const int n_base = (wid & 1) * 64;                                          \
    const uint32_t* Wwhi = reinterpret_cast<const uint32_t*>(sm + SM_WHI);      \
    const uint32_t* Wwlo = reinterpret_cast<const uint32_t*>(sm + SM_WLO);      \
    const uint32_t* Awhi = reinterpret_cast<const uint32_t*>(sm + SM_AHI);      \
    const uint32_t* Awlo = reinterpret_cast<const uint32_t*>(sm + SM_ALO);      \
    float acc[2][8][4];                                                         \
    _Pragma("unroll")                                                           \
    for (int mf = 0; mf < 2; mf++)                                              \
        _Pragma("unroll")                                                       \
        for (int nf = 0; nf < 8; nf++)                                          \
            _Pragma("unroll")                                                   \
            for (int q = 0; q < 4; q++) acc[mf][nf][q] = 0.f;                   \
    const int arow = tid >> 1;                                                  \
    const int aseg = tid & 1;                                                   \
    for (int kc = 0; kc < 4; kc++) {                                            \
        __syncthreads();                                                        \
        __VA_ARGS__;                                                            \
        __syncthreads();                                                        \
        _Pragma("unroll")                                                       \
        for (int ks = 0; ks < 4; ks++) {                                        \
            const int kwl = ks * 8;                                             \
            const int kwg = kc * 32 + ks * 8;                                   \
            uint32_t ahi[2][4];                                                 \
            uint32_t alo[2][4];                                                 \
            uint32_t bhi[8][2];                                                 \
            uint32_t blo[8][2];                                                 \
            _Pragma("unroll")                                                   \
            for (int mf = 0; mf < 2; mf++) {                                    \
                int r0 = (m_base + mf * 16 + g) * 36 + kwl + tig;               \
                int r1 = r0 + 8 * 36;                                           \
                ahi[mf][0] = Awhi[r0];     ahi[mf][1] = Awhi[r1];               \
                ahi[mf][2] = Awhi[r0 + 4]; ahi[mf][3] = Awhi[r1 + 4];           \
                alo[mf][0] = Awlo[r0];     alo[mf][1] = Awlo[r1];               \
                alo[mf][2] = Awlo[r0 + 4]; alo[mf][3] = Awlo[r1 + 4];           \
            }                                                                   \
            _Pragma("unroll")                                                   \
            for (int nf = 0; nf < 8; nf++) {                                    \
                int rb = (n_base + nf * 8 + g) * 132 + kwg + tig;               \
                bhi[nf][0] = Wwhi[rb]; bhi[nf][1] = Wwhi[rb + 4];               \
                blo[nf][0] = Wwlo[rb]; blo[nf][1] = Wwlo[rb + 4];               \
            }                                                                   \
            _Pragma("unroll")                                                   \
            for (int mf = 0; mf < 2; mf++)                                      \
                _Pragma("unroll")                                               \
                for (int nf = 0; nf < 8; nf++) {                                \
                    MMA_BF16(acc[mf][nf], ahi[mf], bhi[nf]);                    \
                    MMA_BF16(acc[mf][nf], ahi[mf], blo[nf]);                    \
                    MMA_BF16(acc[mf][nf], alo[mf], bhi[nf]);                    \
                }                                                               \
        }                                                                       \
    }                                                                           \
    const float* bias = reinterpret_cast<const float*>(sm + SM_BIAS);           \
    _Pragma("unroll")                                                           \
    for (int mf = 0; mf < 2; mf++) {                                            \
        int row0 = m_base + mf * 16 + g;                                        \
        _Pragma("unroll")                                                       \
        for (int nf = 0; nf < 8; nf++) {                                        \
            int col = n_base + nf * 8 + tig * 2;                                \
            float2 o0 = { acc[mf][nf][0] + bias[col],                           \
                          acc[mf][nf][1] + bias[col + 1] };                     \
            float2 o1 = { acc[mf][nf][2] + bias[col],                           \
                          acc[mf][nf][3] + bias[col + 1] };                     \
            *reinterpret_cast<float2*>(&Crows[(size_t)row0 * 256 + bn + col]) = o0;      \
            *reinterpret_cast<float2*>(&Crows[(size_t)(row0 + 8) * 256 + bn + col]) = o1;\
        }                                                                       \
    }

// A from precomputed bf16 hi/lo (worker path, validated R7)
__device__ __forceinline__ void mma_tile_bf16(
    const __nv_bfloat16* __restrict__ Ahig,
    const __nv_bfloat16* __restrict__ Alog,
    float* __restrict__ Crows, int bn, char* sm)
{
    MMA_CORE_BODY({
        const uint4* ghi = reinterpret_cast<const uint4*>(
            Ahig + (size_t)arow * 256 + kc * 64 + aseg * 32);
        const uint4* glo = reinterpret_cast<const uint4*>(
            Alog + (size_t)arow * 256 + kc * 64 + aseg * 32);
        uint4* shi = reinterpret_cast<uint4*>(sm + SM_AHI + arow * (AROWB*2) + aseg * 64);
        uint4* slo = reinterpret_cast<uint4*>(sm + SM_ALO + arow * (AROWB*2) + aseg * 64);
        _Pragma("unroll")
        for (int q = 0; q < 4; q++) { shi[q] = ghi[q]; slo[q] = glo[q]; }
    });
}

// A from fp32, converted to hi/lo during staging (phase-A path)
__device__ __forceinline__ void mma_tile_f32(
    const float* __restrict__ Arows,
    float* __restrict__ Crows, int bn, char* sm)
{
    MMA_CORE_BODY({
        const float4* gf = reinterpret_cast<const float4*>(
            Arows + (size_t)arow * 256 + kc * 64 + aseg * 32);
        uint32_t hw[16];
        uint32_t lw[16];
        _Pragma("unroll")
        for (int q = 0; q < 8; q++) {
            float4 f = gf[q];
            __nv_bfloat162 h0 = __floats2bfloat162_rn(f.x, f.y);
            __nv_bfloat162 h1 = __floats2bfloat162_rn(f.z, f.w);
            float lx = f.x - __bfloat162float(h0.x);
            float ly = f.y - __bfloat162float(h0.y);
            float lz = f.z - __bfloat162float(h1.x);
            float lw2 = f.w - __bfloat162float(h1.y);
            __nv_bfloat162 l0 = __floats2bfloat162_rn(lx, ly);
            __nv_bfloat162 l1 = __floats2bfloat162_rn(lz, lw2);
            hw[2*q]   = *reinterpret_cast<uint32_t*>(&h0);
            hw[2*q+1] = *reinterpret_cast<uint32_t*>(&h1);
            lw[2*q]   = *reinterpret_cast<uint32_t*>(&l0);
            lw[2*q+1] = *reinterpret_cast<uint32_t*>(&l1);
        }
        uint4* shi = reinterpret_cast<uint4*>(sm + SM_AHI + arow * (AROWB*2) + aseg * 64);
        uint4* slo = reinterpret_cast<uint4*>(sm + SM_ALO + arow * (AROWB*2) + aseg * 64);
        _Pragma("unroll")
        for (int q = 0; q < 4; q++) {
            shi[q] = make_uint4(hw[4*q], hw[4*q+1], hw[4*q+2], hw[4*q+3]);
            slo[q] = make_uint4(lw[4*q], lw[4*q+1], lw[4*q+2], lw[4*q+3]);
        }
    });
}

// ---------------------------------------------------------------------------
// Scan role: thread j owns output j. W row j: 176 floats in regs (88 u64),
// 80 in smem (20 float4, stride 21 -> conflict-free phases).
// Double-buffered h, 1 barrier/step, fast tanh. Polls every 16 steps (8-LA).
// Progress published every 2 steps with a fence.
// ---------------------------------------------------------------------------
__device__ __forceinline__ void scan_role(
    const float* __restrict__ xp, const float* __restrict__ Whh,
    int b, float4* Wt,
    __nv_bfloat16* outhi, __nv_bfloat16* outlo, int* prog_out,   // layer1
    float* outf,                                                  // layer2
    const int* poll_flags)
{
    __shared__ __align__(16) float hbuf[2][HID];
    const int j = threadIdx.x;

    unsigned long long w2[88];
    const float4* wrow = reinterpret_cast<const float4*>(Whh + (size_t)j * HID);
    #pragma unroll
    for (int i = 0; i < 44; i++) {
        F4U v; v.v = wrow[i];
        w2[2*i] = v.u[0]; w2[2*i+1] = v.u[1];
    }
    #pragma unroll
    for (int i = 0; i < 20; i++)
        Wt[j * 21 + i] = wrow[44 + i];

    hbuf[0][j] = 0.f;
    __syncthreads();

    const float4* wsrow  = &Wt[j * 21];
    const size_t  stride = (size_t)BATCH * HID;
    const size_t  base   = (size_t)b * HID + j;

    int cur = 0;
    for (int t = 0; t < T_STEPS; t++) {
        if (poll_flags && (t & 15) == 0) {
            int c0 = t >> 1;
            if (j < 16) {
                const int* f = &poll_flags[(c0 + (j >> 1)) * 2 + (j & 1)];
                while (ld_acq(f) == 0) __nanosleep(100);
            }
            __syncthreads();
        }

        float xv = xp[(size_t)t * stride + base];

        const float4* h4 = reinterpret_cast<const float4*>(hbuf[cur]);
        unsigned long long a0 = 0ull, a1 = 0ull, a2 = 0ull, a3 = 0ull;

        #pragma unroll
        for (int i = 0; i < 44; i += 2) {      // k in [0,176): W in regs
            F4U hv0; hv0.v = h4[i];
            a0 = ffma2(w2[2*i],   hv0.u[0], a0);
            a1 = ffma2(w2[2*i+1], hv0.u[1], a1);
            F4U hv1; hv1.v = h4[i+1];
            a2 = ffma2(w2[2*i+2], hv1.u[0], a2);
            a3 = ffma2(w2[2*i+3], hv1.u[1], a3);
        }
        #pragma unroll
        for (int i = 0; i < 20; i += 2) {      // k in [176,256): W in smem
            F4U wv0; wv0.v = wsrow[i];
            F4U hv0; hv0.v = h4[44 + i];
            a0 = ffma2(wv0.u[0], hv0.u[0], a0);
            a1 = ffma2(wv0.u[1], hv0.u[1], a1);
            F4U wv1; wv1.v = wsrow[i+1];
            F4U hv1; hv1.v = h4[45 + i];
            a2 = ffma2(wv1.u[0], hv1.u[0], a2);
            a3 = ffma2(wv1.u[1], hv1.u[1], a3);
        }

        float2 s0 = up2(a0), s1 = up2(a1), s2 = up2(a2), s3 = up2(a3);
        float sum = ((s0.x + s0.y) + (s1.x + s1.y))
                  + ((s2.x + s2.y) + (s3.x + s3.y)) + xv;
        float h = fast_tanh(sum);

        hbuf[cur ^ 1][j] = h;
        if (outf) {
            outf[(size_t)t * stride + base] = h;
        } else {
            __nv_bfloat16 hv = __float2bfloat16(h);
            outhi[(size_t)t * stride + base] = hv;
            outlo[(size_t)t * stride + base] =
                __float2bfloat16(h - __bfloat162float(hv));
        }
        __syncthreads();
        if (prog_out && (t & 1) && j == 0) {
            __threadfence();
            st_rel(prog_out, t + 1);
        }
        cur ^= 1;
    }
}

// ---------------------------------------------------------------------------
// Pipeline (R12 schedule): 148 CTAs, everything after prep.
//   bid 0..63   : layer-1 scan (polls g_xp0flag) -> h1 bf16, publishes prog1
//   bid 64..147 : FIRST phase-A streams (xp0 = x@W_ih0^T+b, sets g_xp0flag)
//     then bid 64..127 : layer-2 scan (polls g_midflag) -> out
//          bid 128..147: HMMA xp1 workers (poll prog1, set g_midflag)
// ---------------------------------------------------------------------------
__global__ __launch_bounds__(256, 1) void pipeline_kernel(
    const float* __restrict__ x,
    const float* __restrict__ W_hh0,
    const float* __restrict__ b_ih0, const float* __restrict__ b_hh0,
    const float* __restrict__ b_ih1, const float* __restrict__ b_hh1,
    const float* __restrict__ W_hh1,
    float* __restrict__ out)
{
    extern __shared__ char sm[];
    const int bid = blockIdx.x;
    const int tid = threadIdx.x;

    if (bid < 64) {
        scan_role(g_buf0, W_hh0, bid, reinterpret_cast<float4*>(sm),
                  g_h1hi, g_h1lo, &g_prog1[bid], nullptr, g_xp0flag);
        return;
    }

    // ---- phase A: xp0 chunks in ascending order ----
    {
        const int s = bid - 64;          // 0..83
        const int half = s & 1;
        const int bn = half * 128;
        const int stream = s >> 1;       // 0..41
        mma_setup_w(sm, g_Whi[0], g_Wlo[0], bn, b_ih0, b_hh0);
        for (int c = stream; c < NCHUNK; c += NPA) {
            mma_tile_f32(x + (size_t)c * 128 * 256,
                         g_buf0 + (size_t)c * 128 * 256, bn, sm);
            __syncthreads();
            if (tid == 0) st_rel(&g_xp0flag[c * 2 + half], 1);
        }
        __syncthreads();
    }

    if (bid < 128) {
        // ---- layer-2 scan ----
        scan_role(g_buf2, W_hh1, bid - 64, reinterpret_cast<float4*>(sm),
                  nullptr, nullptr, nullptr, out, g_midflag);
    } else {
        // ---- xp1 workers ----
        const int w = bid - 128;         // 0..19
        const int half = w & 1;
        const int bn = half * 128;
        const int stream = w >> 1;       // 0..9
        mma_setup_w(sm, g_Whi[1], g_Wlo[1], bn, b_ih1, b_hh1);
        for (int c = stream; c < NCHUNK; c += NWSTR) {
            if (tid < BATCH)
                while (ld_acq(&g_prog1[tid]) < 2 * c + 2) __nanosleep(200);
            __syncthreads();
            mma_tile_bf16(g_h1hi + (size_t)c * 128 * 256,
                          g_h1lo + (size_t)c * 128 * 256,
                          g_buf2 + (size_t)c * 128 * 256, bn, sm);
            __syncthreads();
            if (tid == 0) st_rel(&g_midflag[c * 2 + half], 1);
        }
    }
}

// ---------------------------------------------------------------------------
extern "C" void kernel_launch(void* const* d_in, const int* in_sizes, int n_in,
                              void* d_out, int out_size)
{
    const float* x     = (const float*)d_in[0];
    const float* W_ih0 = (const float*)d_in[1];
    const float* W_hh0 = (const float*)d_in[2];
    const float* b_ih0 = (const float*)d_in[3];
    const float* b_hh0 = (const float*)d_in[4];
    const float* W_ih1 = (const float*)d_in[5];
    const float* W_hh1 = (const float*)d_in[6];
    const float* b_ih1 = (const float*)d_in[7];
    const float* b_hh1 = (const float*)d_in[8];
    float* out = (float*)d_out;

    cudaFuncSetAttribute(pipeline_kernel,
                         cudaFuncAttributeMaxDynamicSharedMemorySize, GEMM_SMEM);

    prep_kernel<<<64, 256>>>(W_ih0, W_ih1);
    pipeline_kernel<<<148, 256, GEMM_SMEM>>>(
        x, W_hh0, b_ih0, b_hh0, b_ih1, b_hh1, W_hh1, out);
}

// round 15
// speedup vs baseline: 1.0234x; 1.0234x over previous
#include <cuda_runtime.h>
#include <cuda_bf16.h>
#include <cstdint>

#define T_STEPS 2048
#define BATCH   64
#define HID     256
#define MROWS   (T_STEPS * BATCH)   // 131072
#define NCHUNK  1024                // 128-row (=2-step) chunks
#define NTILE   (NCHUNK * 2)
#define NPA     42                  // phase-A streams (84 CTAs / 2 halves)
#define NWSTR   10                  // worker streams (20 CTAs / 2 halves)

// GEMM smem layout (bytes) — validated in R7
#define SM_BIAS  0
#define SM_WHI   1024
#define WROWB    264
#define WBYTES   (128 * WROWB * 2)
#define SM_WLO   (SM_WHI + WBYTES)
#define SM_AHI   (SM_WLO + WBYTES)
#define AROWB    72
#define ABYTES   (128 * AROWB * 2)
#define SM_ALO   (SM_AHI + ABYTES)
#define GEMM_SMEM (SM_ALO + ABYTES)  // 173056

// Scan smem: Wt stride 25 float4 (96 floats W + pad): 256*25*16 = 102400 < GEMM_SMEM

__device__ float g_buf0[(size_t)MROWS * HID];   // xp0 fp32
__device__ float g_buf2[(size_t)MROWS * HID];   // xp1 fp32
__device__ __nv_bfloat16 g_h1hi[(size_t)MROWS * HID];
__device__ __nv_bfloat16 g_h1lo[(size_t)MROWS * HID];
__device__ __nv_bfloat16 g_Whi[2][HID * HID];
__device__ __nv_bfloat16 g_Wlo[2][HID * HID];
__device__ int g_prog1[BATCH];
__device__ int g_xp0flag[NTILE];
__device__ int g_midflag[NTILE];

// ---------------------------------------------------------------------------
union F4U { float4 v; unsigned long long u[2]; };
__device__ __forceinline__ unsigned long long ffma2(
    unsigned long long a, unsigned long long b, unsigned long long c)
{
    unsigned long long d;
    asm("fma.rn.f32x2 %0, %1, %2, %3;" : "=l"(d) : "l"(a), "l"(b), "l"(c));
    return d;
}
__device__ __forceinline__ float2 up2(unsigned long long v)
{
    float2 r;
    asm("mov.b64 {%0, %1}, %2;" : "=f"(r.x), "=f"(r.y) : "l"(v));
    return r;
}
__device__ __forceinline__ int ld_acq(const int* p)
{
    int v;
    asm volatile("ld.acquire.gpu.global.b32 %0, [%1];" : "=r"(v) : "l"(p) : "memory");
    return v;
}
__device__ __forceinline__ void st_rel(int* p, int v)
{
    asm volatile("st.release.gpu.global.b32 [%0], %1;" :: "l"(p), "r"(v) : "memory");
}
// Fast tanh: e = exp(2x) via MUFU.EX2, tanh = (e-1)/(e+1) via fast divide.
// Abs error ~1e-7; clamp avoids overflow (tanh(+-15) == +-1 in fp32).
__device__ __forceinline__ float fast_tanh(float x)
{
    x = fminf(fmaxf(x, -15.0f), 15.0f);
    float e = __expf(2.0f * x);
    return __fdividef(e - 1.0f, e + 1.0f);
}

#define MMA_BF16(d, a, b) \
    asm volatile("mma.sync.aligned.m16n8k16.row.col.f32.bf16.bf16.f32 " \
        "{%0,%1,%2,%3},{%4,%5,%6,%7},{%8,%9},{%0,%1,%2,%3};" \
        : "+f"((d)[0]), "+f"((d)[1]), "+f"((d)[2]), "+f"((d)[3]) \
        : "r"((a)[0]), "r"((a)[1]), "r"((a)[2]), "r"((a)[3]), \
          "r"((b)[0]), "r"((b)[1]))

// ---------------------------------------------------------------------------
// Prep: zero flags, convert W_ih0/W_ih1 to bf16 hi/lo. (~10us)
// ---------------------------------------------------------------------------
__global__ void prep_kernel(const float* __restrict__ Wih0,
                            const float* __restrict__ Wih1)
{
    int idx = blockIdx.x * blockDim.x + threadIdx.x;
    int nthr = gridDim.x * blockDim.x;
    for (int i = idx; i < NTILE; i += nthr) { g_xp0flag[i] = 0; g_midflag[i] = 0; }
    if (idx < BATCH) g_prog1[idx] = 0;
    for (int i = idx; i < 2 * HID * HID; i += nthr) {
        int m = i >> 16, e = i & 0xFFFF;
        float w = (m == 0 ? Wih0 : Wih1)[e];
        __nv_bfloat16 hi = __float2bfloat16(w);
        g_Whi[m][e] = hi;
        g_Wlo[m][e] = __float2bfloat16(w - __bfloat162float(hi));
    }
}

// ---------------------------------------------------------------------------
// Stage W half + bias into smem (validated R7)
// ---------------------------------------------------------------------------
__device__ __forceinline__ void mma_setup_w(
    char* sm, const __nv_bfloat16* Whig, const __nv_bfloat16* Wlog, int bn,
    const float* b1, const float* b2)
{
    const int tid = threadIdx.x;
    const int row = tid >> 1;
    const int seg = tid & 1;
    const uint4* ghi = reinterpret_cast<const uint4*>(
        Whig + (size_t)(bn + row) * 256 + seg * 128);
    const uint4* glo = reinterpret_cast<const uint4*>(
        Wlog + (size_t)(bn + row) * 256 + seg * 128);
    uint4* shi = reinterpret_cast<uint4*>(sm + SM_WHI + row * (WROWB*2) + seg * 256);
    uint4* slo = reinterpret_cast<uint4*>(sm + SM_WLO + row * (WROWB*2) + seg * 256);
    #pragma unroll
    for (int q = 0; q < 16; q++) { shi[q] = ghi[q]; slo[q] = glo[q]; }
    if (tid < 128) {
        int n = bn + tid;
        reinterpret_cast<float*>(sm + SM_BIAS)[tid] = b1[n] + b2[n];
    }
    __syncthreads();
}

// ---------------------------------------------------------------------------
// Shared MMA compute core (validated R7/R10). Variadic: commas OK in STAGE_A.
// ---------------------------------------------------------------------------
#define MMA_CORE_BODY(...)                                                      \
    const int tid  = threadIdx.x;                                               \
    const int lane = tid & 31;                                                  \
    const int wid  = tid >> 5;                                                  \
    const int g    = lane >> 2;                                                 \
    const int tig  = lane & 3;                                                  \
    const int m_base = (wid >> 1) * 32;                                         \
    const int n_base = (wid & 1) * 64;                                          \
    const uint32_t* Wwhi = reinterpret_cast<const uint32_t*>(sm + SM_WHI);      \
    const uint32_t* Wwlo = reinterpret_cast<const uint32_t*>(sm + SM_WLO);      \
    const uint32_t* Awhi = reinterpret_cast<const uint32_t*>(sm + SM_AHI);      \
    const uint32_t* Awlo = reinterpret_cast<const uint32_t*>(sm + SM_ALO);      \
    float acc[2][8][4];                                                         \
    _Pragma("unroll")                                                           \
    for (int mf = 0; mf < 2; mf++)                                              \
        _Pragma("unroll")                                                       \
        for (int nf = 0; nf < 8; nf++)                                          \
            _Pragma("unroll")                                                   \
            for (int q = 0; q < 4; q++) acc[mf][nf][q] = 0.f;                   \
    const int arow = tid >> 1;                                                  \
    const int aseg = tid & 1;                                                   \
    for (int kc = 0; kc < 4; kc++) {                                            \
        __syncthreads();                                                        \
        __VA_ARGS__;                                                            \
        __syncthreads();                                                        \
        _Pragma("unroll")                                                       \
        for (int ks = 0; ks < 4; ks++) {                                        \
            const int kwl = ks * 8;                                             \
            const int kwg = kc * 32 + ks * 8;                                   \
            uint32_t ahi[2][4];                                                 \
            uint32_t alo[2][4];                                                 \
            uint32_t bhi[8][2];                                                 \
            uint32_t blo[8][2];                                                 \
            _Pragma("unroll")                                                   \
            for (int mf = 0; mf < 2; mf++) {                                    \
                int r0 = (m_base + mf * 16 + g) * 36 + kwl + tig;               \
                int r1 = r0 + 8 * 36;                                           \
                ahi[mf][0] = Awhi[r0];     ahi[mf][1] = Awhi[r1];               \
                ahi[mf][2] = Awhi[r0 + 4]; ahi[mf][3] = Awhi[r1 + 4];           \
                alo[mf][0] = Awlo[r0];     alo[mf][1] = Awlo[r1];               \
                alo[mf][2] = Awlo[r0 + 4]; alo[mf][3] = Awlo[r1 + 4];           \
            }                                                                   \
            _Pragma("unroll")                                                   \
            for (int nf = 0; nf < 8; nf++) {                                    \
                int rb = (n_base + nf * 8 + g) * 132 + kwg + tig;               \
                bhi[nf][0] = Wwhi[rb]; bhi[nf][1] = Wwhi[rb + 4];               \
                blo[nf][0] = Wwlo[rb]; blo[nf][1] = Wwlo[rb + 4];               \
            }                                                                   \
            _Pragma("unroll")                                                   \
            for (int mf = 0; mf < 2; mf++)                                      \
                _Pragma("unroll")                                               \
                for (int nf = 0; nf < 8; nf++) {                                \
                    MMA_BF16(acc[mf][nf], ahi[mf], bhi[nf]);                    \
                    MMA_BF16(acc[mf][nf], ahi[mf], blo[nf]);                    \
                    MMA_BF16(acc[mf][nf], alo[mf], bhi[nf]);                    \
                }                                                               \
        }                                                                       \
    }                                                                           \
    const float* bias = reinterpret_cast<const float*>(sm + SM_BIAS);           \
    _Pragma("unroll")                                                           \
    for (int mf = 0; mf < 2; mf++) {                                            \
        int row0 = m_base + mf * 16 + g;                                        \
        _Pragma("unroll")                                                       \
        for (int nf = 0; nf < 8; nf++) {                                        \
            int col = n_base + nf * 8 + tig * 2;                                \
            float2 o0 = { acc[mf][nf][0] + bias[col],                           \
                          acc[mf][nf][1] + bias[col + 1] };                     \
            float2 o1 = { acc[mf][nf][2] + bias[col],                           \
                          acc[mf][nf][3] + bias[col + 1] };                     \
            *reinterpret_cast<float2*>(&Crows[(size_t)row0 * 256 + bn + col]) = o0;      \
            *reinterpret_cast<float2*>(&Crows[(size_t)(row0 + 8) * 256 + bn + col]) = o1;\
        }                                                                       \
    }

// A from precomputed bf16 hi/lo (worker path, validated R7)
__device__ __forceinline__ void mma_tile_bf16(
    const __nv_bfloat16* __restrict__ Ahig,
    const __nv_bfloat16* __restrict__ Alog,
    float* __restrict__ Crows, int bn, char* sm)
{
    MMA_CORE_BODY({
        const uint4* ghi = reinterpret_cast<const uint4*>(
            Ahig + (size_t)arow * 256 + kc * 64 + aseg * 32);
        const uint4* glo = reinterpret_cast<const uint4*>(
            Alog + (size_t)arow * 256 + kc * 64 + aseg * 32);
        uint4* shi = reinterpret_cast<uint4*>(sm + SM_AHI + arow * (AROWB*2) + aseg * 64);
        uint4* slo = reinterpret_cast<uint4*>(sm + SM_ALO + arow * (AROWB*2) + aseg * 64);
        _Pragma("unroll")
        for (int q = 0; q < 4; q++) { shi[q] = ghi[q]; slo[q] = glo[q]; }
    });
}

// A from fp32, converted to hi/lo during staging (phase-A path)
__device__ __forceinline__ void mma_tile_f32(
    const float* __restrict__ Arows,
    float* __restrict__ Crows, int bn, char* sm)
{
    MMA_CORE_BODY({
        const float4* gf = reinterpret_cast<const float4*>(
            Arows + (size_t)arow * 256 + kc * 64 + aseg * 32);
        uint32_t hw[16];
        uint32_t lw[16];
        _Pragma("unroll")
        for (int q = 0; q < 8; q++) {
            float4 f = gf[q];
            __nv_bfloat162 h0 = __floats2bfloat162_rn(f.x, f.y);
            __nv_bfloat162 h1 = __floats2bfloat162_rn(f.z, f.w);
            float lx = f.x - __bfloat162float(h0.x);
            float ly = f.y - __bfloat162float(h0.y);
            float lz = f.z - __bfloat162float(h1.x);
            float lw2 = f.w - __bfloat162float(h1.y);
            __nv_bfloat162 l0 = __floats2bfloat162_rn(lx, ly);
            __nv_bfloat162 l1 = __floats2bfloat162_rn(lz, lw2);
            hw[2*q]   = *reinterpret_cast<uint32_t*>(&h0);
            hw[2*q+1] = *reinterpret_cast<uint32_t*>(&h1);
            lw[2*q]   = *reinterpret_cast<uint32_t*>(&l0);
            lw[2*q+1] = *reinterpret_cast<uint32_t*>(&l1);
        }
        uint4* shi = reinterpret_cast<uint4*>(sm + SM_AHI + arow * (AROWB*2) + aseg * 64);
        uint4* slo = reinterpret_cast<uint4*>(sm + SM_ALO + arow * (AROWB*2) + aseg * 64);
        _Pragma("unroll")
        for (int q = 0; q < 4; q++) {
            shi[q] = make_uint4(hw[4*q], hw[4*q+1], hw[4*q+2], hw[4*q+3]);
            slo[q] = make_uint4(lw[4*q], lw[4*q+1], lw[4*q+2], lw[4*q+3]);
        }
    });
}

// ---------------------------------------------------------------------------
// Scan role (R12-winning config): W row j: 160 floats in regs (80 u64),
// 96 in smem (24 float4, stride 25). Double-buffered h, 1 barrier/step.
// fast_tanh on the activation. Polls every 16 steps (8-chunk lookahead).
// Progress published every 2 steps with a fence.
// ---------------------------------------------------------------------------
__device__ __forceinline__ void scan_role(
    const float* __restrict__ xp, const float* __restrict__ Whh,
    int b, float4* Wt,
    __nv_bfloat16* outhi, __nv_bfloat16* outlo, int* prog_out,   // layer1
    float* outf,                                                  // layer2
    const int* poll_flags)
{
    __shared__ __align__(16) float hbuf[2][HID];
    const int j = threadIdx.x;

    unsigned long long w2[80];
    const float4* wrow = reinterpret_cast<const float4*>(Whh + (size_t)j * HID);
    #pragma unroll
    for (int i = 0; i < 40; i++) {
        F4U v; v.v = wrow[i];
        w2[2*i] = v.u[0]; w2[2*i+1] = v.u[1];
    }
    #pragma unroll
    for (int i = 0; i < 24; i++)
        Wt[j * 25 + i] = wrow[40 + i];

    hbuf[0][j] = 0.f;
    __syncthreads();

    const float4* wsrow  = &Wt[j * 25];
    const size_t  stride = (size_t)BATCH * HID;
    const size_t  base   = (size_t)b * HID + j;

    int cur = 0;
    for (int t = 0; t < T_STEPS; t++) {
        if (poll_flags && (t & 15) == 0) {
            int c0 = t >> 1;
            if (j < 16) {
                const int* f = &poll_flags[(c0 + (j >> 1)) * 2 + (j & 1)];
                while (ld_acq(f) == 0) __nanosleep(100);
            }
            __syncthreads();
        }

        float xv = xp[(size_t)t * stride + base];

        const float4* h4 = reinterpret_cast<const float4*>(hbuf[cur]);
        unsigned long long a0 = 0ull, a1 = 0ull, a2 = 0ull, a3 = 0ull;

        #pragma unroll
        for (int i = 0; i < 40; i += 2) {      // k in [0,160): W in regs
            F4U hv0; hv0.v = h4[i];
            a0 = ffma2(w2[2*i],   hv0.u[0], a0);
            a1 = ffma2(w2[2*i+1], hv0.u[1], a1);
            F4U hv1; hv1.v = h4[i+1];
            a2 = ffma2(w2[2*i+2], hv1.u[0], a2);
            a3 = ffma2(w2[2*i+3], hv1.u[1], a3);
        }
        #pragma unroll
        for (int i = 0; i < 24; i += 2) {      // k in [160,256): W in smem
            F4U wv0; wv0.v = wsrow[i];
            F4U hv0; hv0.v = h4[40 + i];
            a0 = ffma2(wv0.u[0], hv0.u[0], a0);
            a1 = ffma2(wv0.u[1], hv0.u[1], a1);
            F4U wv1; wv1.v = wsrow[i+1];
            F4U hv1; hv1.v = h4[41 + i];
            a2 = ffma2(wv1.u[0], hv1.u[0], a2);
            a3 = ffma2(wv1.u[1], hv1.u[1], a3);
        }

        float2 s0 = up2(a0), s1 = up2(a1), s2 = up2(a2), s3 = up2(a3);
        float sum = ((s0.x + s0.y) + (s1.x + s1.y))
                  + ((s2.x + s2.y) + (s3.x + s3.y)) + xv;
        float h = fast_tanh(sum);

        hbuf[cur ^ 1][j] = h;
        if (outf) {
            outf[(size_t)t * stride + base] = h;
        } else {
            __nv_bfloat16 hv = __float2bfloat16(h);
            outhi[(size_t)t * stride + base] = hv;
            outlo[(size_t)t * stride + base] =
                __float2bfloat16(h - __bfloat162float(hv));
        }
        __syncthreads();
        if (prog_out && (t & 1) && j == 0) {
            __threadfence();
            st_rel(prog_out, t + 1);
        }
        cur ^= 1;
    }
}

// ---------------------------------------------------------------------------
// Pipeline (R12 schedule): 148 CTAs, everything after prep.
//   bid 0..63   : layer-1 scan (polls g_xp0flag) -> h1 bf16, publishes prog1
//   bid 64..147 : FIRST phase-A streams (xp0 = x@W_ih0^T+b, sets g_xp0flag)
//     then bid 64..127 : layer-2 scan (polls g_midflag) -> out
//          bid 128..147: HMMA xp1 workers (poll prog1, set g_midflag)
// ---------------------------------------------------------------------------
__global__ __launch_bounds__(256, 1) void pipeline_kernel(
    const float* __restrict__ x,
    const float* __restrict__ W_hh0,
    const float* __restrict__ b_ih0, const float* __restrict__ b_hh0,
    const float* __restrict__ b_ih1, const float* __restrict__ b_hh1,
    const float* __restrict__ W_hh1,
    float* __restrict__ out)
{
    extern __shared__ char sm[];
    const int bid = blockIdx.x;
    const int tid = threadIdx.x;

    if (bid < 64) {
        scan_role(g_buf0, W_hh0, bid, reinterpret_cast<float4*>(sm),
                  g_h1hi, g_h1lo, &g_prog1[bid], nullptr, g_xp0flag);
        return;
    }

    // ---- phase A: xp0 chunks in ascending order ----
    {
        const int s = bid - 64;          // 0..83
        const int half = s & 1;
        const int bn = half * 128;
        const int stream = s >> 1;       // 0..41
        mma_setup_w(sm, g_Whi[0], g_Wlo[0], bn, b_ih0, b_hh0);
        for (int c = stream; c < NCHUNK; c += NPA) {
            mma_tile_f32(x + (size_t)c * 128 * 256,
                         g_buf0 + (size_t)c * 128 * 256, bn, sm);
            __syncthreads();
            if (tid == 0) st_rel(&g_xp0flag[c * 2 + half], 1);
        }
        __syncthreads();
    }

    if (bid < 128) {
        // ---- layer-2 scan ----
        scan_role(g_buf2, W_hh1, bid - 64, reinterpret_cast<float4*>(sm),
                  nullptr, nullptr, nullptr, out, g_midflag);
    } else {
        // ---- xp1 workers ----
        const int w = bid - 128;         // 0..19
        const int half = w & 1;
        const int bn = half * 128;
        const int stream = w >> 1;       // 0..9
        mma_setup_w(sm, g_Whi[1], g_Wlo[1], bn, b_ih1, b_hh1);
        for (int c = stream; c < NCHUNK; c += NWSTR) {
            if (tid < BATCH)
                while (ld_acq(&g_prog1[tid]) < 2 * c + 2) __nanosleep(200);
            __syncthreads();
            mma_tile_bf16(g_h1hi + (size_t)c * 128 * 256,
                          g_h1lo + (size_t)c * 128 * 256,
                          g_buf2 + (size_t)c * 128 * 256, bn, sm);
            __syncthreads();
            if (tid == 0) st_rel(&g_midflag[c * 2 + half], 1);
        }
    }
}

// ---------------------------------------------------------------------------
extern "C" void kernel_launch(void* const* d_in, const int* in_sizes, int n_in,
                              void* d_out, int out_size)
{
    const float* x     = (const float*)d_in[0];
    const float* W_ih0 = (const float*)d_in[1];
    const float* W_hh0 = (const float*)d_in[2];
    const float* b_ih0 = (const float*)d_in[3];
    const float* b_hh0 = (const float*)d_in[4];
    const float* W_ih1 = (const float*)d_in[5];
    const float* W_hh1 = (const float*)d_in[6];
    const float* b_ih1 = (const float*)d_in[7];
    const float* b_hh1 = (const float*)d_in[8];
    float* out = (float*)d_out;

    cudaFuncSetAttribute(pipeline_kernel,
                         cudaFuncAttributeMaxDynamicSharedMemorySize, GEMM_SMEM);

    prep_kernel<<<64, 256>>>(W_ih0, W_ih1);
    pipeline_kernel<<<148, 256, GEMM_SMEM>>>(
        x, W_hh0, b_ih0, b_hh0, b_ih1, b_hh1, W_hh1, out);
}

// round 16
// speedup vs baseline: 1.0591x; 1.0348x over previous
#include <cuda_runtime.h>
#include <cuda_bf16.h>
#include <cstdint>

#define T_STEPS 2048
#define BATCH   64
#define HID     256
#define MROWS   (T_STEPS * BATCH)   // 131072
#define NCHUNK  1024                // 128-row (=2-step) chunks
#define NTILE   (NCHUNK * 2)
#define NWSTR   10                  // xp1 worker streams (20 CTAs / 2 halves)

// GEMM smem layout (bytes) — validated in R7
#define SM_BIAS  0
#define SM_WHI   1024
#define WROWB    264
#define WBYTES   (128 * WROWB * 2)
#define SM_WLO   (SM_WHI + WBYTES)
#define SM_AHI   (SM_WLO + WBYTES)
#define AROWB    72
#define ABYTES   (128 * AROWB * 2)
#define SM_ALO   (SM_AHI + ABYTES)
#define GEMM_SMEM (SM_ALO + ABYTES)  // 173056

// Scan dynamic smem: Wt 256 rows x 23 float4 (21 used + pad) = 94208 < GEMM_SMEM

__device__ float g_buf0[(size_t)MROWS * HID];   // xp0 fp32
__device__ float g_buf2[(size_t)MROWS * HID];   // xp1 fp32
__device__ __nv_bfloat16 g_h1hi[(size_t)MROWS * HID];
__device__ __nv_bfloat16 g_h1lo[(size_t)MROWS * HID];
__device__ __nv_bfloat16 g_Whi[2][HID * HID];
__device__ __nv_bfloat16 g_Wlo[2][HID * HID];
__device__ int g_prog1[BATCH];
__device__ int g_midflag[NTILE];

// ---------------------------------------------------------------------------
union F4U { float4 v; unsigned long long u[2]; };
__device__ __forceinline__ unsigned long long ffma2(
    unsigned long long a, unsigned long long b, unsigned long long c)
{
    unsigned long long d;
    asm("fma.rn.f32x2 %0, %1, %2, %3;" : "=l"(d) : "l"(a), "l"(b), "l"(c));
    return d;
}
__device__ __forceinline__ float2 up2(unsigned long long v)
{
    float2 r;
    asm("mov.b64 {%0, %1}, %2;" : "=f"(r.x), "=f"(r.y) : "l"(v));
    return r;
}
__device__ __forceinline__ int ld_acq(const int* p)
{
    int v;
    asm volatile("ld.acquire.gpu.global.b32 %0, [%1];" : "=r"(v) : "l"(p) : "memory");
    return v;
}
__device__ __forceinline__ void st_rel(int* p, int v)
{
    asm volatile("st.release.gpu.global.b32 [%0], %1;" :: "l"(p), "r"(v) : "memory");
}
__device__ __forceinline__ float fast_tanh(float x)
{
    x = fminf(fmaxf(x, -15.0f), 15.0f);
    float e = __expf(2.0f * x);
    return __fdividef(e - 1.0f, e + 1.0f);
}

#define MMA_BF16(d, a, b) \
    asm volatile("mma.sync.aligned.m16n8k16.row.col.f32.bf16.bf16.f32 " \
        "{%0,%1,%2,%3},{%4,%5,%6,%7},{%8,%9},{%0,%1,%2,%3};" \
        : "+f"((d)[0]), "+f"((d)[1]), "+f"((d)[2]), "+f"((d)[3]) \
        : "r"((a)[0]), "r"((a)[1]), "r"((a)[2]), "r"((a)[3]), \
          "r"((b)[0]), "r"((b)[1]))

// ---------------------------------------------------------------------------
// Prep: zero flags, convert W_ih0/W_ih1 to bf16 hi/lo.
// ---------------------------------------------------------------------------
__global__ void prep_kernel(const float* __restrict__ Wih0,
                            const float* __restrict__ Wih1)
{
    int idx = blockIdx.x * blockDim.x + threadIdx.x;
    int nthr = gridDim.x * blockDim.x;
    for (int i = idx; i < NTILE; i += nthr) g_midflag[i] = 0;
    if (idx < BATCH) g_prog1[idx] = 0;
    for (int i = idx; i < 2 * HID * HID; i += nthr) {
        int m = i >> 16, e = i & 0xFFFF;
        float w = (m == 0 ? Wih0 : Wih1)[e];
        __nv_bfloat16 hi = __float2bfloat16(w);
        g_Whi[m][e] = hi;
        g_Wlo[m][e] = __float2bfloat16(w - __bfloat162float(hi));
    }
}

// ---------------------------------------------------------------------------
// Stage W half + bias into smem. Guarded for >256-thread blocks.
// ---------------------------------------------------------------------------
__device__ __forceinline__ void mma_setup_w(
    char* sm, const __nv_bfloat16* Whig, const __nv_bfloat16* Wlog, int bn,
    const float* b1, const float* b2)
{
    const int tid = threadIdx.x;
    if (tid < 256) {
        const int row = tid >> 1;
        const int seg = tid & 1;
        const uint4* ghi = reinterpret_cast<const uint4*>(
            Whig + (size_t)(bn + row) * 256 + seg * 128);
        const uint4* glo = reinterpret_cast<const uint4*>(
            Wlog + (size_t)(bn + row) * 256 + seg * 128);
        uint4* shi = reinterpret_cast<uint4*>(sm + SM_WHI + row * (WROWB*2) + seg * 256);
        uint4* slo = reinterpret_cast<uint4*>(sm + SM_WLO + row * (WROWB*2) + seg * 256);
        #pragma unroll
        for (int q = 0; q < 16; q++) { shi[q] = ghi[q]; slo[q] = glo[q]; }
        if (tid < 128) {
            int n = bn + tid;
            reinterpret_cast<float*>(sm + SM_BIAS)[tid] = b1[n] + b2[n];
        }
    }
    __syncthreads();
}

// ---------------------------------------------------------------------------
// Shared MMA compute core (validated R7/R10), now tolerant of blockDim>256:
// threads >=256 participate only in barriers.
// ---------------------------------------------------------------------------
#define MMA_CORE_BODY(...)                                                      \
    const int tid  = threadIdx.x;                                               \
    const bool act = tid < 256;                                                 \
    const int lane = tid & 31;                                                  \
    const int wid  = (tid >> 5) & 7;                                            \
    const int g    = lane >> 2;                                                 \
    const int tig  = lane & 3;                                                  \
    const int m_base = (wid >> 1) * 32;                                         \
    const int n_base = (wid & 1) * 64;                                          \
    const uint32_t* Wwhi = reinterpret_cast<const uint32_t*>(sm + SM_WHI);      \
    const uint32_t* Wwlo = reinterpret_cast<const uint32_t*>(sm + SM_WLO);      \
    const uint32_t* Awhi = reinterpret_cast<const uint32_t*>(sm + SM_AHI);      \
    const uint32_t* Awlo = reinterpret_cast<const uint32_t*>(sm + SM_ALO);      \
    float acc[2][8][4];                                                         \
    _Pragma("unroll")                                                           \
    for (int mf = 0; mf < 2; mf++)                                              \
        _Pragma("unroll")                                                       \
        for (int nf = 0; nf < 8; nf++)                                          \
            _Pragma("unroll")                                                   \
            for (int q = 0; q < 4; q++) acc[mf][nf][q] = 0.f;                   \
    const int arow = (tid >> 1) & 127;                                          \
    const int aseg = tid & 1;                                                   \
    for (int kc = 0; kc < 4; kc++) {                                            \
        __syncthreads();                                                        \
        if (act) { __VA_ARGS__; }                                               \
        __syncthreads();                                                        \
        if (act) {                                                              \
            _Pragma("unroll")                                                   \
            for (int ks = 0; ks < 4; ks++) {                                    \
                const int kwl = ks * 8;                                         \
                const int kwg = kc * 32 + ks * 8;                               \
                uint32_t ahi[2][4];                                             \
                uint32_t alo[2][4];                                             \
                uint32_t bhi[8][2];                                             \
                uint32_t blo[8][2];                                             \
                _Pragma("unroll")                                               \
                for (int mf = 0; mf < 2; mf++) {                                \
                    int r0 = (m_base + mf * 16 + g) * 36 + kwl + tig;           \
                    int r1 = r0 + 8 * 36;                                       \
                    ahi[mf][0] = Awhi[r0];     ahi[mf][1] = Awhi[r1];           \
                    ahi[mf][2] = Awhi[r0 + 4]; ahi[mf][3] = Awhi[r1 + 4];       \
                    alo[mf][0] = Awlo[r0];     alo[mf][1] = Awlo[r1];           \
                    alo[mf][2] = Awlo[r0 + 4]; alo[mf][3] = Awlo[r1 + 4];       \
                }                                                               \
                _Pragma("unroll")                                               \
                for (int nf = 0; nf < 8; nf++) {                                \
                    int rb = (n_base + nf * 8 + g) * 132 + kwg + tig;           \
                    bhi[nf][0] = Wwhi[rb]; bhi[nf][1] = Wwhi[rb + 4];           \
                    blo[nf][0] = Wwlo[rb]; blo[nf][1] = Wwlo[rb + 4];           \
                }                                                               \
                _Pragma("unroll")                                               \
                for (int mf = 0; mf < 2; mf++)                                  \
                    _Pragma("unroll")                                           \
                    for (int nf = 0; nf < 8; nf++) {                            \
                        MMA_BF16(acc[mf][nf], ahi[mf], bhi[nf]);                \
                        MMA_BF16(acc[mf][nf], ahi[mf], blo[nf]);                \
                        MMA_BF16(acc[mf][nf], alo[mf], bhi[nf]);                \
                    }                                                           \
            }                                                                   \
        }                                                                       \
    }                                                                           \
    if (act) {                                                                  \
        const float* bias = reinterpret_cast<const float*>(sm + SM_BIAS);       \
        _Pragma("unroll")                                                       \
        for (int mf = 0; mf < 2; mf++) {                                        \
            int row0 = m_base + mf * 16 + g;                                    \
            _Pragma("unroll")                                                   \
            for (int nf = 0; nf < 8; nf++) {                                    \
                int col = n_base + nf * 8 + tig * 2;                            \
                float2 o0 = { acc[mf][nf][0] + bias[col],                       \
                              acc[mf][nf][1] + bias[col + 1] };                 \
                float2 o1 = { acc[mf][nf][2] + bias[col],                       \
                              acc[mf][nf][3] + bias[col + 1] };                 \
                *reinterpret_cast<float2*>(&Crows[(size_t)row0 * 256 + bn + col]) = o0;      \
                *reinterpret_cast<float2*>(&Crows[(size_t)(row0 + 8) * 256 + bn + col]) = o1;\
            }                                                                   \
        }                                                                       \
    }

// A from precomputed bf16 hi/lo (xp1 worker path)
__device__ __forceinline__ void mma_tile_bf16(
    const __nv_bfloat16* __restrict__ Ahig,
    const __nv_bfloat16* __restrict__ Alog,
    float* __restrict__ Crows, int bn, char* sm)
{
    MMA_CORE_BODY({
        const uint4* ghi = reinterpret_cast<const uint4*>(
            Ahig + (size_t)arow * 256 + kc * 64 + aseg * 32);
        const uint4* glo = reinterpret_cast<const uint4*>(
            Alog + (size_t)arow * 256 + kc * 64 + aseg * 32);
        uint4* shi = reinterpret_cast<uint4*>(sm + SM_AHI + arow * (AROWB*2) + aseg * 64);
        uint4* slo = reinterpret_cast<uint4*>(sm + SM_ALO + arow * (AROWB*2) + aseg * 64);
        _Pragma("unroll")
        for (int q = 0; q < 4; q++) { shi[q] = ghi[q]; slo[q] = glo[q]; }
    });
}

// A from fp32, converted during staging (phase-A path)
__device__ __forceinline__ void mma_tile_f32(
    const float* __restrict__ Arows,
    float* __restrict__ Crows, int bn, char* sm)
{
    MMA_CORE_BODY({
        const float4* gf = reinterpret_cast<const float4*>(
            Arows + (size_t)arow * 256 + kc * 64 + aseg * 32);
        uint32_t hw[16];
        uint32_t lw[16];
        _Pragma("unroll")
        for (int q = 0; q < 8; q++) {
            float4 f = gf[q];
            __nv_bfloat162 h0 = __floats2bfloat162_rn(f.x, f.y);
            __nv_bfloat162 h1 = __floats2bfloat162_rn(f.z, f.w);
            float lx = f.x - __bfloat162float(h0.x);
            float ly = f.y - __bfloat162float(h0.y);
            float lz = f.z - __bfloat162float(h1.x);
            float lw2 = f.w - __bfloat162float(h1.y);
            __nv_bfloat162 l0 = __floats2bfloat162_rn(lx, ly);
            __nv_bfloat162 l1 = __floats2bfloat162_rn(lz, lw2);
            hw[2*q]   = *reinterpret_cast<uint32_t*>(&h0);
            hw[2*q+1] = *reinterpret_cast<uint32_t*>(&h1);
            lw[2*q]   = *reinterpret_cast<uint32_t*>(&l0);
            lw[2*q+1] = *reinterpret_cast<uint32_t*>(&l1);
        }
        uint4* shi = reinterpret_cast<uint4*>(sm + SM_AHI + arow * (AROWB*2) + aseg * 64);
        uint4* slo = reinterpret_cast<uint4*>(sm + SM_ALO + arow * (AROWB*2) + aseg * 64);
        _Pragma("unroll")
        for (int q = 0; q < 4; q++) {
            shi[q] = make_uint4(hw[4*q], hw[4*q+1], hw[4*q+2], hw[4*q+3]);
            slo[q] = make_uint4(lw[4*q], lw[4*q+1], lw[4*q+2], lw[4*q+3]);
        }
    });
}

// ---------------------------------------------------------------------------
// Phase A: xp0 = x @ W_ih0^T + bias, 148 CTAs x 256 threads (no reg cap).
// ---------------------------------------------------------------------------
__global__ __launch_bounds__(256, 1) void phase_a_kernel(
    const float* __restrict__ x,
    const float* __restrict__ b_ih0, const float* __restrict__ b_hh0)
{
    extern __shared__ char sm[];
    const int half = blockIdx.x & 1;
    const int stream = blockIdx.x >> 1;   // 0..73
    const int bn = half * 128;
    mma_setup_w(sm, g_Whi[0], g_Wlo[0], bn, b_ih0, b_hh0);
    for (int c = stream; c < NCHUNK; c += 74)
        mma_tile_f32(x + (size_t)c * 128 * 256,
                     g_buf0 + (size_t)c * 128 * 256, bn, sm);
}

// ---------------------------------------------------------------------------
// 384-thread hybrid K-split scan.
//   owners  (tid<256, output j=tid): K [0,112) regs (56 u64),
//           K [112,196) smem (21 f4, stride 23).
//   helpers (tid 256..383, outputs 2m/2m+1): K [196,256) regs (60 u64).
// Per step: partials -> pbuf (helpers) -> barrier -> owners finish h
//           -> barrier. Poll every 16 steps (8-chunk lookahead).
// ---------------------------------------------------------------------------
__device__ __forceinline__ void scan_role(
    const float* __restrict__ xp, const float* __restrict__ Whh,
    int b, float4* Wt,
    __nv_bfloat16* outhi, __nv_bfloat16* outlo, int* prog_out,   // layer1
    float* outf,                                                  // layer2
    const int* poll_flags)
{
    __shared__ __align__(16) float hbuf[HID];
    __shared__ __align__(16) float pbuf[HID];
    const int tid = threadIdx.x;
    const bool owner = tid < 256;
    const int m = tid - 256;

    unsigned long long wreg[60];
    if (owner) {
        const float4* wrow = reinterpret_cast<const float4*>(Whh + (size_t)tid * HID);
        #pragma unroll
        for (int i = 0; i < 28; i++) {
            F4U v; v.v = wrow[i];
            wreg[2*i] = v.u[0]; wreg[2*i+1] = v.u[1];
        }
        #pragma unroll
        for (int i = 0; i < 21; i++)
            Wt[tid * 23 + i] = wrow[28 + i];
        hbuf[tid] = 0.f;
    } else {
        const float4* w0 = reinterpret_cast<const float4*>(Whh + (size_t)(2*m) * HID);
        const float4* w1 = reinterpret_cast<const float4*>(Whh + (size_t)(2*m+1) * HID);
        #pragma unroll
        for (int i = 0; i < 15; i++) {
            F4U v; v.v = w0[49 + i];
            wreg[2*i] = v.u[0]; wreg[2*i+1] = v.u[1];
        }
        #pragma unroll
        for (int i = 0; i < 15; i++) {
            F4U v; v.v = w1[49 + i];
            wreg[30 + 2*i] = v.u[0]; wreg[31 + 2*i] = v.u[1];
        }
    }
    __syncthreads();

    const float4* h4     = reinterpret_cast<const float4*>(hbuf);
    const float4* wsrow  = &Wt[tid * 23];   // owners only
    const size_t  stride = (size_t)BATCH * HID;
    const size_t  base   = (size_t)b * HID + tid;   // owners: output index j==tid

    for (int t = 0; t < T_STEPS; t++) {
        if (poll_flags && (t & 15) == 0) {
            int c0 = t >> 1;
            if (tid < 16) {
                const int* f = &poll_flags[(c0 + (tid >> 1)) * 2 + (tid & 1)];
                while (ld_acq(f) == 0) __nanosleep(100);
            }
            __syncthreads();
        }

        if (owner) {
            float xv = xp[(size_t)t * stride + base];

            unsigned long long a0 = 0ull, a1 = 0ull, a2 = 0ull, a3 = 0ull;
            #pragma unroll
            for (int i = 0; i < 28; i += 2) {          // K [0,112): regs
                F4U hv0; hv0.v = h4[i];
                a0 = ffma2(wreg[2*i],   hv0.u[0], a0);
                a1 = ffma2(wreg[2*i+1], hv0.u[1], a1);
                F4U hv1; hv1.v = h4[i+1];
                a2 = ffma2(wreg[2*i+2], hv1.u[0], a2);
                a3 = ffma2(wreg[2*i+3], hv1.u[1], a3);
            }
            #pragma unroll
            for (int i = 0; i < 21; i++) {             // K [112,196): smem
                F4U wv; wv.v = wsrow[i];
                F4U hv; hv.v = h4[28 + i];
                if (i & 1) {
                    a2 = ffma2(wv.u[0], hv.u[0], a2);
                    a3 = ffma2(wv.u[1], hv.u[1], a3);
                } else {
                    a0 = ffma2(wv.u[0], hv.u[0], a0);
                    a1 = ffma2(wv.u[1], hv.u[1], a1);
                }
            }
            float2 s0 = up2(a0), s1 = up2(a1), s2 = up2(a2), s3 = up2(a3);
            float own = ((s0.x + s0.y) + (s1.x + s1.y))
                      + ((s2.x + s2.y) + (s3.x + s3.y));

            __syncthreads();                            // A: pbuf ready
            float h = fast_tanh(xv + own + pbuf[tid]);
            hbuf[tid] = h;
            if (outf) {
                outf[(size_t)t * stride + base] = h;
            } else {
                __nv_bfloat16 hv = __float2bfloat16(h);
                outhi[(size_t)t * stride + base] = hv;
                outlo[(size_t)t * stride + base] =
                    __float2bfloat16(h - __bfloat162float(hv));
            }
        } else {
            unsigned long long a0 = 0ull, a1 = 0ull, b0 = 0ull, b1 = 0ull;
            #pragma unroll
            for (int i = 0; i < 15; i++) {             // K [196,256): regs, 2 rows
                F4U hv; hv.v = h4[49 + i];
                a0 = ffma2(wreg[2*i],      hv.u[0], a0);
                a1 = ffma2(wreg[2*i+1],    hv.u[1], a1);
                b0 = ffma2(wreg[30 + 2*i], hv.u[0], b0);
                b1 = ffma2(wreg[31 + 2*i], hv.u[1], b1);
            }
            float2 s0 = up2(a0), s1 = up2(a1), s2 = up2(b0), s3 = up2(b1);
            float2 p;
            p.x = (s0.x + s0.y) + (s1.x + s1.y);
            p.y = (s2.x + s2.y) + (s3.x + s3.y);
            *reinterpret_cast<float2*>(&pbuf[2*m]) = p;
            __syncthreads();                            // A
        }
        __syncthreads();                                // B: h visible
        if (prog_out && (t & 1) && tid == 0) {
            __threadfence();
            st_rel(prog_out, t + 1);
        }
    }
}

// ---------------------------------------------------------------------------
// Pipeline: 148 CTAs x 384 threads (phase A already done).
//   bid 0..63   : layer-1 scan -> h1 bf16, publishes prog1
//   bid 64..127 : layer-2 scan (polls g_midflag) -> out
//   bid 128..147: HMMA xp1 workers (poll prog1, set g_midflag)
// ---------------------------------------------------------------------------
__global__ __launch_bounds__(384, 1) void pipeline_kernel(
    const float* __restrict__ W_hh0,
    const float* __restrict__ b_ih1, const float* __restrict__ b_hh1,
    const float* __restrict__ W_hh1,
    float* __restrict__ out)
{
    extern __shared__ char sm[];
    const int bid = blockIdx.x;
    const int tid = threadIdx.x;

    if (bid < 64) {
        scan_role(g_buf0, W_hh0, bid, reinterpret_cast<float4*>(sm),
                  g_h1hi, g_h1lo, &g_prog1[bid], nullptr, nullptr);
    } else if (bid < 128) {
        scan_role(g_buf2, W_hh1, bid - 64, reinterpret_cast<float4*>(sm),
                  nullptr, nullptr, nullptr, out, g_midflag);
    } else {
        const int w = bid - 128;         // 0..19
        const int half = w & 1;
        const int bn = half * 128;
        const int stream = w >> 1;       // 0..9
        mma_setup_w(sm, g_Whi[1], g_Wlo[1], bn, b_ih1, b_hh1);
        for (int c = stream; c < NCHUNK; c += NWSTR) {
            if (tid < BATCH)
                while (ld_acq(&g_prog1[tid]) < 2 * c + 2) __nanosleep(200);
            __syncthreads();
            mma_tile_bf16(g_h1hi + (size_t)c * 128 * 256,
                          g_h1lo + (size_t)c * 128 * 256,
                          g_buf2 + (size_t)c * 128 * 256, bn, sm);
            __syncthreads();
            if (tid == 0) st_rel(&g_midflag[c * 2 + half], 1);
        }
    }
}

// ---------------------------------------------------------------------------
extern "C" void kernel_launch(void* const* d_in, const int* in_sizes, int n_in,
                              void* d_out, int out_size)
{
    const float* x     = (const float*)d_in[0];
    const float* W_ih0 = (const float*)d_in[1];
    const float* W_hh0 = (const float*)d_in[2];
    const float* b_ih0 = (const float*)d_in[3];
    const float* b_hh0 = (const float*)d_in[4];
    const float* W_ih1 = (const float*)d_in[5];
    const float* W_hh1 = (const float*)d_in[6];
    const float* b_ih1 = (const float*)d_in[7];
    const float* b_hh1 = (const float*)d_in[8];
    float* out = (float*)d_out;

    cudaFuncSetAttribute(phase_a_kernel,
                         cudaFuncAttributeMaxDynamicSharedMemorySize, GEMM_SMEM);
    cudaFuncSetAttribute(pipeline_kernel,
                         cudaFuncAttributeMaxDynamicSharedMemorySize, GEMM_SMEM);

    prep_kernel<<<64, 256>>>(W_ih0, W_ih1);
    phase_a_kernel<<<148, 256, GEMM_SMEM>>>(x, b_ih0, b_hh0);
    pipeline_kernel<<<148, 384, GEMM_SMEM>>>(W_hh0, b_ih1, b_hh1, W_hh1, out);
}

// round 17
// speedup vs baseline: 1.1068x; 1.0451x over previous
#include <cuda_runtime.h>
#include <cuda_bf16.h>
#include <cstdint>

#define T_STEPS 2048
#define BATCH   64
#define HID     256
#define MROWS   (T_STEPS * BATCH)   // 131072
#define NCHUNK  1024                // 128-row (=2-step) chunks
#define NTILE   (NCHUNK * 2)
#define NPA     42                  // phase-A streams (84 CTAs / 2 halves)
#define NWSTR   10                  // xp1 worker streams (20 CTAs / 2 halves)

// GEMM smem layout (bytes) — validated in R7
#define SM_BIAS  0
#define SM_WHI   1024
#define WROWB    264
#define WBYTES   (128 * WROWB * 2)
#define SM_WLO   (SM_WHI + WBYTES)
#define SM_AHI   (SM_WLO + WBYTES)
#define AROWB    72
#define ABYTES   (128 * AROWB * 2)
#define SM_ALO   (SM_AHI + ABYTES)
#define GEMM_SMEM (SM_ALO + ABYTES)  // 173056

// Scan dynamic smem: Wt 256 rows x 23 float4 = 94208 < GEMM_SMEM

__device__ float g_buf0[(size_t)MROWS * HID];   // xp0 fp32
__device__ float g_buf2[(size_t)MROWS * HID];   // xp1 fp32
__device__ __nv_bfloat16 g_h1hi[(size_t)MROWS * HID];
__device__ __nv_bfloat16 g_h1lo[(size_t)MROWS * HID];
__device__ __nv_bfloat16 g_Whi[2][HID * HID];
__device__ __nv_bfloat16 g_Wlo[2][HID * HID];
__device__ int g_prog1[BATCH];
__device__ int g_xp0flag[NTILE];
__device__ int g_midflag[NTILE];

// ---------------------------------------------------------------------------
union F4U { float4 v; unsigned long long u[2]; };
__device__ __forceinline__ unsigned long long ffma2(
    unsigned long long a, unsigned long long b, unsigned long long c)
{
    unsigned long long d;
    asm("fma.rn.f32x2 %0, %1, %2, %3;" : "=l"(d) : "l"(a), "l"(b), "l"(c));
    return d;
}
__device__ __forceinline__ float2 up2(unsigned long long v)
{
    float2 r;
    asm("mov.b64 {%0, %1}, %2;" : "=f"(r.x), "=f"(r.y) : "l"(v));
    return r;
}
__device__ __forceinline__ int ld_acq(const int* p)
{
    int v;
    asm volatile("ld.acquire.gpu.global.b32 %0, [%1];" : "=r"(v) : "l"(p) : "memory");
    return v;
}
__device__ __forceinline__ void st_rel(int* p, int v)
{
    asm volatile("st.release.gpu.global.b32 [%0], %1;" :: "l"(p), "r"(v) : "memory");
}
__device__ __forceinline__ float fast_tanh(float x)
{
    x = fminf(fmaxf(x, -15.0f), 15.0f);
    float e = __expf(2.0f * x);
    return __fdividef(e - 1.0f, e + 1.0f);
}

#define MMA_BF16(d, a, b) \
    asm volatile("mma.sync.aligned.m16n8k16.row.col.f32.bf16.bf16.f32 " \
        "{%0,%1,%2,%3},{%4,%5,%6,%7},{%8,%9},{%0,%1,%2,%3};" \
        : "+f"((d)[0]), "+f"((d)[1]), "+f"((d)[2]), "+f"((d)[3]) \
        : "r"((a)[0]), "r"((a)[1]), "r"((a)[2]), "r"((a)[3]), \
          "r"((b)[0]), "r"((b)[1]))

// ---------------------------------------------------------------------------
// Prep: zero flags, convert W_ih0/W_ih1 to bf16 hi/lo.
// ---------------------------------------------------------------------------
__global__ void prep_kernel(const float* __restrict__ Wih0,
                            const float* __restrict__ Wih1)
{
    int idx = blockIdx.x * blockDim.x + threadIdx.x;
    int nthr = gridDim.x * blockDim.x;
    for (int i = idx; i < NTILE; i += nthr) { g_xp0flag[i] = 0; g_midflag[i] = 0; }
    if (idx < BATCH) g_prog1[idx] = 0;
    for (int i = idx; i < 2 * HID * HID; i += nthr) {
        int m = i >> 16, e = i & 0xFFFF;
        float w = (m == 0 ? Wih0 : Wih1)[e];
        __nv_bfloat16 hi = __float2bfloat16(w);
        g_Whi[m][e] = hi;
        g_Wlo[m][e] = __float2bfloat16(w - __bfloat162float(hi));
    }
}

// ---------------------------------------------------------------------------
// Stage W half + bias into smem. Guarded for >256-thread blocks.
// ---------------------------------------------------------------------------
__device__ __forceinline__ void mma_setup_w(
    char* sm, const __nv_bfloat16* Whig, const __nv_bfloat16* Wlog, int bn,
    const float* b1, const float* b2)
{
    const int tid = threadIdx.x;
    if (tid < 256) {
        const int row = tid >> 1;
        const int seg = tid & 1;
        const uint4* ghi = reinterpret_cast<const uint4*>(
            Whig + (size_t)(bn + row) * 256 + seg * 128);
        const uint4* glo = reinterpret_cast<const uint4*>(
            Wlog + (size_t)(bn + row) * 256 + seg * 128);
        uint4* shi = reinterpret_cast<uint4*>(sm + SM_WHI + row * (WROWB*2) + seg * 256);
        uint4* slo = reinterpret_cast<uint4*>(sm + SM_WLO + row * (WROWB*2) + seg * 256);
        #pragma unroll
        for (int q = 0; q < 16; q++) { shi[q] = ghi[q]; slo[q] = glo[q]; }
        if (tid < 128) {
            int n = bn + tid;
            reinterpret_cast<float*>(sm + SM_BIAS)[tid] = b1[n] + b2[n];
        }
    }
    __syncthreads();
}

// ---------------------------------------------------------------------------
// Shared MMA compute core (validated R7/R10), tolerant of blockDim>256:
// threads >=256 participate only in barriers.
// ---------------------------------------------------------------------------
#define MMA_CORE_BODY(...)                                                      \
    const int tid  = threadIdx.x;                                               \
    const bool act = tid < 256;                                                 \
    const int lane = tid & 31;                                                  \
    const int wid  = (tid >> 5) & 7;                                            \
    const int g    = lane >> 2;                                                 \
    const int tig  = lane & 3;                                                  \
    const int m_base = (wid >> 1) * 32;                                         \
    const int n_base = (wid & 1) * 64;                                          \
    const uint32_t* Wwhi = reinterpret_cast<const uint32_t*>(sm + SM_WHI);      \
    const uint32_t* Wwlo = reinterpret_cast<const uint32_t*>(sm + SM_WLO);      \
    const uint32_t* Awhi = reinterpret_cast<const uint32_t*>(sm + SM_AHI);      \
    const uint32_t* Awlo = reinterpret_cast<const uint32_t*>(sm + SM_ALO);      \
    float acc[2][8][4];                                                         \
    _Pragma("unroll")                                                           \
    for (int mf = 0; mf < 2; mf++)                                              \
        _Pragma("unroll")                                                       \
        for (int nf = 0; nf < 8; nf++)                                          \
            _Pragma("unroll")                                                   \
            for (int q = 0; q < 4; q++) acc[mf][nf][q] = 0.f;                   \
    const int arow = (tid >> 1) & 127;                                          \
    const int aseg = tid & 1;                                                   \
    for (int kc = 0; kc < 4; kc++) {                                            \
        __syncthreads();                                                        \
        if (act) { __VA_ARGS__; }                                               \
        __syncthreads();                                                        \
        if (act) {                                                              \
            _Pragma("unroll")                                                   \
            for (int ks = 0; ks < 4; ks++) {                                    \
                const int kwl = ks * 8;                                         \
                const int kwg = kc * 32 + ks * 8;                               \
                uint32_t ahi[2][4];                                             \
                uint32_t alo[2][4];                                             \
                uint32_t bhi[8][2];                                             \
                uint32_t blo[8][2];                                             \
                _Pragma("unroll")                                               \
                for (int mf = 0; mf < 2; mf++) {                                \
                    int r0 = (m_base + mf * 16 + g) * 36 + kwl + tig;           \
                    int r1 = r0 + 8 * 36;                                       \
                    ahi[mf][0] = Awhi[r0];     ahi[mf][1] = Awhi[r1];           \
                    ahi[mf][2] = Awhi[r0 + 4]; ahi[mf][3] = Awhi[r1 + 4];       \
                    alo[mf][0] = Awlo[r0];     alo[mf][1] = Awlo[r1];           \
                    alo[mf][2] = Awlo[r0 + 4]; alo[mf][3] = Awlo[r1 + 4];       \
                }                                                               \
                _Pragma("unroll")                                               \
                for (int nf = 0; nf < 8; nf++) {                                \
                    int rb = (n_base + nf * 8 + g) * 132 + kwg + tig;           \
                    bhi[nf][0] = Wwhi[rb]; bhi[nf][1] = Wwhi[rb + 4];           \
                    blo[nf][0] = Wwlo[rb]; blo[nf][1] = Wwlo[rb + 4];           \
                }                                                               \
                _Pragma("unroll")                                               \
                for (int mf = 0; mf < 2; mf++)                                  \
                    _Pragma("unroll")                                           \
                    for (int nf = 0; nf < 8; nf++) {                            \
                        MMA_BF16(acc[mf][nf], ahi[mf], bhi[nf]);                \
                        MMA_BF16(acc[mf][nf], ahi[mf], blo[nf]);                \
                        MMA_BF16(acc[mf][nf], alo[mf], bhi[nf]);                \
                    }                                                           \
            }                                                                   \
        }                                                                       \
    }                                                                           \
    if (act) {                                                                  \
        const float* bias = reinterpret_cast<const float*>(sm + SM_BIAS);       \
        _Pragma("unroll")                                                       \
        for (int mf = 0; mf < 2; mf++) {                                        \
            int row0 = m_base + mf * 16 + g;                                    \
            _Pragma("unroll")                                                   \
            for (int nf = 0; nf < 8; nf++) {                                    \
                int col = n_base + nf * 8 + tig * 2;                            \
                float2 o0 = { acc[mf][nf][0] + bias[col],                       \
                              acc[mf][nf][1] + bias[col + 1] };                 \
                float2 o1 = { acc[mf][nf][2] + bias[col],                       \
                              acc[mf][nf][3] + bias[col + 1] };                 \
                *reinterpret_cast<float2*>(&Crows[(size_t)row0 * 256 + bn + col]) = o0;      \
                *reinterpret_cast<float2*>(&Crows[(size_t)(row0 + 8) * 256 + bn + col]) = o1;\
            }                                                                   \
        }                                                                       \
    }

// A from precomputed bf16 hi/lo (xp1 worker path)
__device__ __forceinline__ void mma_tile_bf16(
    const __nv_bfloat16* __restrict__ Ahig,
    const __nv_bfloat16* __restrict__ Alog,
    float* __restrict__ Crows, int bn, char* sm)
{
    MMA_CORE_BODY({
        const uint4* ghi = reinterpret_cast<const uint4*>(
            Ahig + (size_t)arow * 256 + kc * 64 + aseg * 32);
        const uint4* glo = reinterpret_cast<const uint4*>(
            Alog + (size_t)arow * 256 + kc * 64 + aseg * 32);
        uint4* shi = reinterpret_cast<uint4*>(sm + SM_AHI + arow * (AROWB*2) + aseg * 64);
        uint4* slo = reinterpret_cast<uint4*>(sm + SM_ALO + arow * (AROWB*2) + aseg * 64);
        _Pragma("unroll")
        for (int q = 0; q < 4; q++) { shi[q] = ghi[q]; slo[q] = glo[q]; }
    });
}

// A from fp32, converted during staging (phase-A path)
__device__ __forceinline__ void mma_tile_f32(
    const float* __restrict__ Arows,
    float* __restrict__ Crows, int bn, char* sm)
{
    MMA_CORE_BODY({
        const float4* gf = reinterpret_cast<const float4*>(
            Arows + (size_t)arow * 256 + kc * 64 + aseg * 32);
        uint32_t hw[16];
        uint32_t lw[16];
        _Pragma("unroll")
        for (int q = 0; q < 8; q++) {
            float4 f = gf[q];
            __nv_bfloat162 h0 = __floats2bfloat162_rn(f.x, f.y);
            __nv_bfloat162 h1 = __floats2bfloat162_rn(f.z, f.w);
            float lx = f.x - __bfloat162float(h0.x);
            float ly = f.y - __bfloat162float(h0.y);
            float lz = f.z - __bfloat162float(h1.x);
            float lw2 = f.w - __bfloat162float(h1.y);
            __nv_bfloat162 l0 = __floats2bfloat162_rn(lx, ly);
            __nv_bfloat162 l1 = __floats2bfloat162_rn(lz, lw2);
            hw[2*q]   = *reinterpret_cast<uint32_t*>(&h0);
            hw[2*q+1] = *reinterpret_cast<uint32_t*>(&h1);
            lw[2*q]   = *reinterpret_cast<uint32_t*>(&l0);
            lw[2*q+1] = *reinterpret_cast<uint32_t*>(&l1);
        }
        uint4* shi = reinterpret_cast<uint4*>(sm + SM_AHI + arow * (AROWB*2) + aseg * 64);
        uint4* slo = reinterpret_cast<uint4*>(sm + SM_ALO + arow * (AROWB*2) + aseg * 64);
        _Pragma("unroll")
        for (int q = 0; q < 4; q++) {
            shi[q] = make_uint4(hw[4*q], hw[4*q+1], hw[4*q+2], hw[4*q+3]);
            slo[q] = make_uint4(lw[4*q], lw[4*q+1], lw[4*q+2], lw[4*q+3]);
        }
    });
}

// ---------------------------------------------------------------------------
// 384-thread hybrid K-split scan (R16-winning config).
//   owners  (tid<256, output j=tid): K [0,112) regs (56 u64),
//           K [112,196) smem (21 f4, stride 23).
//   helpers (tid 256..383, outputs 2m/2m+1): K [196,256) regs (60 u64).
// Per step: helpers -> pbuf -> barrier A -> owners finish -> barrier B.
// Polls input flags every 16 steps (8-chunk lookahead).
// ---------------------------------------------------------------------------
__device__ __forceinline__ void scan_role(
    const float* __restrict__ xp, const float* __restrict__ Whh,
    int b, float4* Wt,
    __nv_bfloat16* outhi, __nv_bfloat16* outlo, int* prog_out,   // layer1
    float* outf,                                                  // layer2
    const int* poll_flags)
{
    __shared__ __align__(16) float hbuf[HID];
    __shared__ __align__(16) float pbuf[HID];
    const int tid = threadIdx.x;
    const bool owner = tid < 256;
    const int m = tid - 256;

    unsigned long long wreg[60];
    if (owner) {
        const float4* wrow = reinterpret_cast<const float4*>(Whh + (size_t)tid * HID);
        #pragma unroll
        for (int i = 0; i < 28; i++) {
            F4U v; v.v = wrow[i];
            wreg[2*i] = v.u[0]; wreg[2*i+1] = v.u[1];
        }
        #pragma unroll
        for (int i = 0; i < 21; i++)
            Wt[tid * 23 + i] = wrow[28 + i];
        hbuf[tid] = 0.f;
    } else {
        const float4* w0 = reinterpret_cast<const float4*>(Whh + (size_t)(2*m) * HID);
        const float4* w1 = reinterpret_cast<const float4*>(Whh + (size_t)(2*m+1) * HID);
        #pragma unroll
        for (int i = 0; i < 15; i++) {
            F4U v; v.v = w0[49 + i];
            wreg[2*i] = v.u[0]; wreg[2*i+1] = v.u[1];
        }
        #pragma unroll
        for (int i = 0; i < 15; i++) {
            F4U v; v.v = w1[49 + i];
            wreg[30 + 2*i] = v.u[0]; wreg[31 + 2*i] = v.u[1];
        }
    }
    __syncthreads();

    const float4* h4     = reinterpret_cast<const float4*>(hbuf);
    const float4* wsrow  = &Wt[tid * 23];
    const size_t  stride = (size_t)BATCH * HID;
    const size_t  base   = (size_t)b * HID + tid;

    for (int t = 0; t < T_STEPS; t++) {
        if (poll_flags && (t & 15) == 0) {
            int c0 = t >> 1;
            if (tid < 16) {
                const int* f = &poll_flags[(c0 + (tid >> 1)) * 2 + (tid & 1)];
                while (ld_acq(f) == 0) __nanosleep(100);
            }
            __syncthreads();
        }

        if (owner) {
            float xv = xp[(size_t)t * stride + base];

            unsigned long long a0 = 0ull, a1 = 0ull, a2 = 0ull, a3 = 0ull;
            #pragma unroll
            for (int i = 0; i < 28; i += 2) {          // K [0,112): regs
                F4U hv0; hv0.v = h4[i];
                a0 = ffma2(wreg[2*i],   hv0.u[0], a0);
                a1 = ffma2(wreg[2*i+1], hv0.u[1], a1);
                F4U hv1; hv1.v = h4[i+1];
                a2 = ffma2(wreg[2*i+2], hv1.u[0], a2);
                a3 = ffma2(wreg[2*i+3], hv1.u[1], a3);
            }
            #pragma unroll
            for (int i = 0; i < 21; i++) {             // K [112,196): smem
                F4U wv; wv.v = wsrow[i];
                F4U hv; hv.v = h4[28 + i];
                if (i & 1) {
                    a2 = ffma2(wv.u[0], hv.u[0], a2);
                    a3 = ffma2(wv.u[1], hv.u[1], a3);
                } else {
                    a0 = ffma2(wv.u[0], hv.u[0], a0);
                    a1 = ffma2(wv.u[1], hv.u[1], a1);
                }
            }
            float2 s0 = up2(a0), s1 = up2(a1), s2 = up2(a2), s3 = up2(a3);
            float own = ((s0.x + s0.y) + (s1.x + s1.y))
                      + ((s2.x + s2.y) + (s3.x + s3.y));

            __syncthreads();                            // A: pbuf ready
            float h = fast_tanh(xv + own + pbuf[tid]);
            hbuf[tid] = h;
            if (outf) {
                outf[(size_t)t * stride + base] = h;
            } else {
                __nv_bfloat16 hv = __float2bfloat16(h);
                outhi[(size_t)t * stride + base] = hv;
                outlo[(size_t)t * stride + base] =
                    __float2bfloat16(h - __bfloat162float(hv));
            }
        } else {
            unsigned long long a0 = 0ull, a1 = 0ull, b0 = 0ull, b1 = 0ull;
            #pragma unroll
            for (int i = 0; i < 15; i++) {             // K [196,256): regs, 2 rows
                F4U hv; hv.v = h4[49 + i];
                a0 = ffma2(wreg[2*i],      hv.u[0], a0);
                a1 = ffma2(wreg[2*i+1],    hv.u[1], a1);
                b0 = ffma2(wreg[30 + 2*i], hv.u[0], b0);
                b1 = ffma2(wreg[31 + 2*i], hv.u[1], b1);
            }
            float2 s0 = up2(a0), s1 = up2(a1), s2 = up2(b0), s3 = up2(b1);
            float2 p;
            p.x = (s0.x + s0.y) + (s1.x + s1.y);
            p.y = (s2.x + s2.y) + (s3.x + s3.y);
            *reinterpret_cast<float2*>(&pbuf[2*m]) = p;
            __syncthreads();                            // A
        }
        __syncthreads();                                // B: h visible
        if (prog_out && (t & 1) && tid == 0) {
            __threadfence();
            st_rel(prog_out, t + 1);
        }
    }
}

// ---------------------------------------------------------------------------
// Pipeline: 148 CTAs x 384 threads, everything after prep.
//   bid 0..63   : layer-1 scan (polls g_xp0flag) -> h1 bf16, publishes prog1
//   bid 64..147 : FIRST phase-A streams (xp0 = x@W_ih0^T+b, sets g_xp0flag)
//     then bid 64..127 : layer-2 scan (polls g_midflag) -> out
//          bid 128..147: HMMA xp1 workers (poll prog1, set g_midflag)
// ---------------------------------------------------------------------------
__global__ __launch_bounds__(384, 1) void pipeline_kernel(
    const float* __restrict__ x,
    const float* __restrict__ W_hh0,
    const float* __restrict__ b_ih0, const float* __restrict__ b_hh0,
    const float* __restrict__ b_ih1, const float* __restrict__ b_hh1,
    const float* __restrict__ W_hh1,
    float* __restrict__ out)
{
    extern __shared__ char sm[];
    const int bid = blockIdx.x;
    const int tid = threadIdx.x;

    if (bid < 64) {
        scan_role(g_buf0, W_hh0, bid, reinterpret_cast<float4*>(sm),
                  g_h1hi, g_h1lo, &g_prog1[bid], nullptr, g_xp0flag);
        return;
    }

    // ---- phase A: xp0 chunks in ascending order ----
    {
        const int s = bid - 64;          // 0..83
        const int half = s & 1;
        const int bn = half * 128;
        const int stream = s >> 1;       // 0..41
        mma_setup_w(sm, g_Whi[0], g_Wlo[0], bn, b_ih0, b_hh0);
        for (int c = stream; c < NCHUNK; c += NPA) {
            mma_tile_f32(x + (size_t)c * 128 * 256,
                         g_buf0 + (size_t)c * 128 * 256, bn, sm);
            __syncthreads();
            if (tid == 0) st_rel(&g_xp0flag[c * 2 + half], 1);
        }
        __syncthreads();
    }

    if (bid < 128) {
        // ---- layer-2 scan ----
        scan_role(g_buf2, W_hh1, bid - 64, reinterpret_cast<float4*>(sm),
                  nullptr, nullptr, nullptr, out, g_midflag);
    } else {
        // ---- xp1 workers ----
        const int w = bid - 128;         // 0..19
        const int half = w & 1;
        const int bn = half * 128;
        const int stream = w >> 1;       // 0..9
        mma_setup_w(sm, g_Whi[1], g_Wlo[1], bn, b_ih1, b_hh1);
        for (int c = stream; c < NCHUNK; c += NWSTR) {
            if (tid < BATCH)
                while (ld_acq(&g_prog1[tid]) < 2 * c + 2) __nanosleep(200);
            __syncthreads();
            mma_tile_bf16(g_h1hi + (size_t)c * 128 * 256,
                          g_h1lo + (size_t)c * 128 * 256,
                          g_buf2 + (size_t)c * 128 * 256, bn, sm);
            __syncthreads();
            if (tid == 0) st_rel(&g_midflag[c * 2 + half], 1);
        }
    }
}

// ---------------------------------------------------------------------------
extern "C" void kernel_launch(void* const* d_in, const int* in_sizes, int n_in,
                              void* d_out, int out_size)
{
    const float* x     = (const float*)d_in[0];
    const float* W_ih0 = (const float*)d_in[1];
    const float* W_hh0 = (const float*)d_in[2];
    const float* b_ih0 = (const float*)d_in[3];
    const float* b_hh0 = (const float*)d_in[4];
    const float* W_ih1 = (const float*)d_in[5];
    const float* W_hh1 = (const float*)d_in[6];
    const float* b_ih1 = (const float*)d_in[7];
    const float* b_hh1 = (const float*)d_in[8];
    float* out = (float*)d_out;

    cudaFuncSetAttribute(pipeline_kernel,
                         cudaFuncAttributeMaxDynamicSharedMemorySize, GEMM_SMEM);

    prep_kernel<<<64, 256>>>(W_ih0, W_ih1);
    pipeline_kernel<<<148, 384, GEMM_SMEM>>>(
        x, W_hh0, b_ih0, b_hh0, b_ih1, b_hh1, W_hh1, out);
}